// round 17
// baseline (speedup 1.0000x reference)
#include <cuda_runtime.h>
#include <cuda_fp16.h>
#include <cstdint>

#define BB 32
#define CC 512
#define LL 16
#define DD 256
#define HH 1024
#define PP 16
#define NHD 8
#define NLL 4

// ---------------- scratch (static device globals; allocation-free) ----------------
__device__ __half g_x  [BB*CC*DD];
__device__ __half g_t0 [BB*CC*HH];
__device__ __half g_t1 [BB*CC*DD];
__device__ __half g_t2h[BB*CC*DD];
__device__ __half g_ch [BB*CC*HH];
__device__ __half g_qh [PP*HH];
__device__ __half g_qw [128*HH];
__device__ float  g_S2 [BB*128*CC];
__device__ __half g_S2h[BB*128*CC];
__device__ __half g_pch[BB*128*HH];
__device__ __half g_p1 [BB*PP*HH];
__device__ float  g_p2 [BB*PP*HH];
__device__ int    g_maskmode;
// half weights
__device__ __half g_hw_in [NLL*768*DD];
__device__ __half g_hw_out[NLL*DD*DD];
__device__ __half g_hw_f1 [NLL*HH*DD];
__device__ __half g_hw_f2 [NLL*DD*HH];
__device__ __half g_hw_th [HH*DD];
__device__ __half g_hw_pa [3*HH*HH];
__device__ __half g_hw_po [HH*HH];
__device__ __half g_hw_pq [PP*HH];

// ---------------- small helpers ----------------
__device__ __forceinline__ uint32_t smem_u32(const void* p) {
    uint32_t a;
    asm("{ .reg .u64 t; cvta.to.shared.u64 t, %1; cvt.u32.u64 %0, t; }" : "=r"(a) : "l"(p));
    return a;
}
__device__ __forceinline__ float gelu_f(float v) {
    return 0.5f * v * (1.f + erff(v * 0.70710678118654752f));
}
__device__ __forceinline__ uint32_t packh2(float lo, float hi) {
    __half2 h = __floats2half2_rn(lo, hi);
    return *(uint32_t*)&h;
}
__device__ __forceinline__ void hmma16(float* c, const uint32_t* a, const uint32_t* b) {
    asm("mma.sync.aligned.m16n8k16.row.col.f32.f16.f16.f32 "
        "{%0,%1,%2,%3}, {%4,%5,%6,%7}, {%8,%9}, {%0,%1,%2,%3};"
        : "+f"(c[0]), "+f"(c[1]), "+f"(c[2]), "+f"(c[3])
        : "r"(a[0]), "r"(a[1]), "r"(a[2]), "r"(a[3]), "r"(b[0]), "r"(b[1]));
}
#define LDM_X4(r0, r1, r2, r3, addr) \
    asm volatile("ldmatrix.sync.aligned.m8n8.x4.shared.b16 {%0,%1,%2,%3}, [%4];" \
        : "=r"(r0), "=r"(r1), "=r"(r2), "=r"(r3) : "r"(addr))
#define LDM_X2(r0, r1, addr) \
    asm volatile("ldmatrix.sync.aligned.m8n8.x2.shared.b16 {%0,%1}, [%2];" \
        : "=r"(r0), "=r"(r1) : "r"(addr))
#define CPA16(dst, src, pred) \
    asm volatile("cp.async.cg.shared.global [%0], [%1], 16, %2;" \
                 :: "r"(dst), "l"(src), "r"((pred) ? 16 : 0))
#define CP_COMMIT() asm volatile("cp.async.commit_group;")
#define CP_WAIT1()  asm volatile("cp.async.wait_group 1;")
#define CP_WAIT0()  asm volatile("cp.async.wait_group 0;")

// ---------------- single-launch fp32->fp16 conversion of ALL weights ----------------
static const int CV_N0 = NLL*768*DD/4;
static const int CV_N1 = CV_N0 + NLL*DD*DD/4;
static const int CV_N2 = CV_N1 + NLL*HH*DD/4;
static const int CV_N3 = CV_N2 + NLL*DD*HH/4;
static const int CV_N4 = CV_N3 + HH*DD/4;
static const int CV_N5 = CV_N4 + 3*HH*HH/4;
static const int CV_N6 = CV_N5 + HH*HH/4;
static const int CV_N7 = CV_N6 + PP*HH/4;

__global__ void cvt_all(
    const float* s0, const float* s1, const float* s2, const float* s3,
    const float* s4, const float* s5, const float* s6, const float* s7,
    __half* d0, __half* d1, __half* d2, __half* d3,
    __half* d4, __half* d5, __half* d6, __half* d7)
{
    for (int i = blockIdx.x * 256 + threadIdx.x; i < CV_N7; i += gridDim.x * 256) {
        const float* s; __half* d; int off;
        if      (i < CV_N0) { s = s0; d = d0; off = i; }
        else if (i < CV_N1) { s = s1; d = d1; off = i - CV_N0; }
        else if (i < CV_N2) { s = s2; d = d2; off = i - CV_N1; }
        else if (i < CV_N3) { s = s3; d = d3; off = i - CV_N2; }
        else if (i < CV_N4) { s = s4; d = d4; off = i - CV_N3; }
        else if (i < CV_N5) { s = s5; d = d5; off = i - CV_N4; }
        else if (i < CV_N6) { s = s6; d = d6; off = i - CV_N5; }
        else                { s = s7; d = d7; off = i - CV_N6; }
        float4 v = ((const float4*)s)[off];
        uint2 u;
        u.x = packh2(v.x, v.y);
        u.y = packh2(v.z, v.w);
        ((uint2*)d)[off] = u;
    }
}

// ============================ fp16 3-stage cp.async + ldmatrix GEMM ============================
template<int ACT, int HASB, int OUTH>
__global__ __launch_bounds__(256, 2) void hgemm(
    const __half* __restrict__ A, const __half* __restrict__ W,
    const float* __restrict__ bias, void* __restrict__ Cp,
    int M, int N, int K, int lda, int ldw, int ldc,
    int nsub, long sAb, long sAs, long sWb, long sWs, long sCb, long sCs,
    long sBs, float alpha)
{
    constexpr int BM = 128, BN = 128, BK = 64, LDH = 72, NST = 3;
    constexpr uint32_t STB = BM * LDH * 2;
    extern __shared__ __half smh[];
    uint32_t base = smem_u32(smh);
    uint32_t asA = base;
    uint32_t wsA = base + NST * STB;

    int tid = threadIdx.x, wid = tid >> 5, lane = tid & 31;
    int warpM = wid >> 2, warpN = wid & 3;
    int g = lane >> 2, tg = lane & 3;
    int bm = blockIdx.y * BM, bn = blockIdx.x * BN;
    int z = blockIdx.z, zb = z / nsub, zs = z % nsub;
    const __half* Ab = A + (size_t)zb * sAb + (size_t)zs * sAs;
    const __half* Wb = W + (size_t)zb * sWb + (size_t)zs * sWs;
    const float* biasB = HASB ? (bias + (size_t)zs * sBs) : bias;

    int arow = (lane & 7) + ((lane & 8) ? 8 : 0);
    int acol = (lane & 16) ? 8 : 0;
    int brow = (lane & 7) + ((lane & 16) ? 8 : 0);
    int bcol = (lane & 8) ? 8 : 0;
    uint32_t aLane = (uint32_t)((warpM * 64 + arow) * LDH + acol) * 2;
    uint32_t bLane = (uint32_t)((warpN * 32 + brow) * LDH + bcol) * 2;

    auto load_stage = [&](int st, int k0) {
        uint32_t ab = asA + (uint32_t)st * STB;
        uint32_t wb = wsA + (uint32_t)st * STB;
        #pragma unroll
        for (int idx = tid; idx < BM * 8; idx += 256) {
            int row = idx >> 3, q = idx & 7;
            int gm = bm + row;
            bool ok = gm < M;
            int gmc = ok ? gm : 0;
            CPA16(ab + (uint32_t)(row * LDH + q * 8) * 2,
                  Ab + (size_t)gmc * lda + k0 + q * 8, ok);
        }
        #pragma unroll
        for (int idx = tid; idx < BN * 8; idx += 256) {
            int row = idx >> 3, q = idx & 7;
            CPA16(wb + (uint32_t)(row * LDH + q * 8) * 2,
                  Wb + (size_t)(bn + row) * ldw + k0 + q * 8, true);
        }
        CP_COMMIT();
    };

    float acc[4][4][4];
    #pragma unroll
    for (int i = 0; i < 4; i++)
        #pragma unroll
        for (int j = 0; j < 4; j++)
            #pragma unroll
            for (int q = 0; q < 4; q++) acc[i][j][q] = 0.f;

    int nk = K / BK;
    load_stage(0, 0);
    if (nk > 1) load_stage(1, BK);

    for (int i = 0; i < nk; i++) {
        if (i + 1 < nk) CP_WAIT1(); else CP_WAIT0();
        __syncthreads();
        if (i + 2 < nk) load_stage((i + 2) % NST, (i + 2) * BK);

        int cur = i % NST;
        uint32_t aB = asA + (uint32_t)cur * STB + aLane;
        uint32_t wB = wsA + (uint32_t)cur * STB + bLane;

        uint32_t af[2][4][4], bf[2][4][2];
        #pragma unroll
        for (int mi = 0; mi < 4; mi++)
            LDM_X4(af[0][mi][0], af[0][mi][1], af[0][mi][2], af[0][mi][3],
                   aB + (uint32_t)(mi * 16 * LDH) * 2);
        LDM_X4(bf[0][0][0], bf[0][0][1], bf[0][1][0], bf[0][1][1], wB);
        LDM_X4(bf[0][2][0], bf[0][2][1], bf[0][3][0], bf[0][3][1],
               wB + (uint32_t)(16 * LDH) * 2);

        #pragma unroll
        for (int ks = 0; ks < 4; ks++) {
            int cb = ks & 1, nb = cb ^ 1;
            if (ks < 3) {
                int kk = (ks + 1) * 16;
                #pragma unroll
                for (int mi = 0; mi < 4; mi++)
                    LDM_X4(af[nb][mi][0], af[nb][mi][1], af[nb][mi][2], af[nb][mi][3],
                           aB + (uint32_t)(mi * 16 * LDH + kk) * 2);
                LDM_X4(bf[nb][0][0], bf[nb][0][1], bf[nb][1][0], bf[nb][1][1],
                       wB + (uint32_t)kk * 2);
                LDM_X4(bf[nb][2][0], bf[nb][2][1], bf[nb][3][0], bf[nb][3][1],
                       wB + (uint32_t)(16 * LDH + kk) * 2);
            }
            #pragma unroll
            for (int mi = 0; mi < 4; mi++)
                #pragma unroll
                for (int nj = 0; nj < 4; nj++)
                    hmma16(acc[mi][nj], af[cb][mi], bf[cb][nj]);
        }
    }

    long cOff = (size_t)zb * sCb + (size_t)zs * sCs;
    #pragma unroll
    for (int mi = 0; mi < 4; mi++) {
        int r0 = bm + warpM * 64 + mi * 16 + g;
        #pragma unroll
        for (int nj = 0; nj < 4; nj++) {
            int c = bn + warpN * 32 + nj * 8 + 2 * tg;
            float b0 = 0.f, b1 = 0.f;
            if (HASB) { b0 = biasB[c]; b1 = biasB[c + 1]; }
            float v0 = acc[mi][nj][0] * alpha + b0;
            float v1 = acc[mi][nj][1] * alpha + b1;
            float v2 = acc[mi][nj][2] * alpha + b0;
            float v3 = acc[mi][nj][3] * alpha + b1;
            if (ACT) { v0 = gelu_f(v0); v1 = gelu_f(v1); v2 = gelu_f(v2); v3 = gelu_f(v3); }
            if (OUTH) {
                __half* Cb = (__half*)Cp + cOff;
                if (r0 < M)     *(uint32_t*)&Cb[(size_t)r0 * ldc + c]       = packh2(v0, v1);
                if (r0 + 8 < M) *(uint32_t*)&Cb[(size_t)(r0 + 8) * ldc + c] = packh2(v2, v3);
            } else {
                float* Cb = (float*)Cp + cOff;
                if (r0 < M)     { Cb[(size_t)r0 * ldc + c] = v0; Cb[(size_t)r0 * ldc + c + 1] = v1; }
                if (r0 + 8 < M) { Cb[(size_t)(r0 + 8) * ldc + c] = v2; Cb[(size_t)(r0 + 8) * ldc + c + 1] = v3; }
            }
        }
    }
}

// ============================ fused GEMM(N=256) + bias + residual + LayerNorm =============
// x[r,:] = LN( A@W^T + bias + x[r,:] ) * lnw + lnb    (in/out x, half)
__global__ __launch_bounds__(512) void hgemm_ln(
    const __half* __restrict__ A, const __half* __restrict__ W,
    const float* __restrict__ bias,
    const float* __restrict__ lnw, const float* __restrict__ lnb,
    __half* __restrict__ x,
    int M, int K, int lda, int ldw)
{
    constexpr int BM = 128, BN = 256, BK = 64, LDH = 72;
    constexpr uint32_t STA = BM * LDH * 2, STW = BN * LDH * 2;
    extern __shared__ __half smh[];
    uint32_t base = smem_u32(smh);
    uint32_t asA = base;                 // 2 stages A
    uint32_t wsA = base + 2 * STA;       // 2 stages W

    int tid = threadIdx.x, wid = tid >> 5, lane = tid & 31;
    int warpM = wid >> 3, warpN = wid & 7;
    int g = lane >> 2, tg = lane & 3;
    int bm = blockIdx.y * BM;

    int arow = (lane & 7) + ((lane & 8) ? 8 : 0);
    int acol = (lane & 16) ? 8 : 0;
    int brow = (lane & 7) + ((lane & 16) ? 8 : 0);
    int bcol = (lane & 8) ? 8 : 0;
    uint32_t aLane = (uint32_t)((warpM * 64 + arow) * LDH + acol) * 2;
    uint32_t bLane = (uint32_t)((warpN * 32 + brow) * LDH + bcol) * 2;

    auto load_stage = [&](int st, int k0) {
        uint32_t ab = asA + (uint32_t)st * STA;
        uint32_t wb = wsA + (uint32_t)st * STW;
        #pragma unroll
        for (int idx = tid; idx < BM * 8; idx += 512) {
            int row = idx >> 3, q = idx & 7;
            CPA16(ab + (uint32_t)(row * LDH + q * 8) * 2,
                  A + (size_t)(bm + row) * lda + k0 + q * 8, true);
        }
        #pragma unroll
        for (int idx = tid; idx < BN * 8; idx += 512) {
            int row = idx >> 3, q = idx & 7;
            CPA16(wb + (uint32_t)(row * LDH + q * 8) * 2,
                  W + (size_t)row * ldw + k0 + q * 8, true);
        }
        CP_COMMIT();
    };

    float acc[4][4][4];
    #pragma unroll
    for (int i = 0; i < 4; i++)
        #pragma unroll
        for (int j = 0; j < 4; j++)
            #pragma unroll
            for (int q = 0; q < 4; q++) acc[i][j][q] = 0.f;

    int nk = K / BK;
    load_stage(0, 0);

    for (int i = 0; i < nk; i++) {
        if (i + 1 < nk) { load_stage((i + 1) & 1, (i + 1) * BK); CP_WAIT1(); }
        else            { CP_WAIT0(); }
        __syncthreads();

        int cur = i & 1;
        uint32_t aB = asA + (uint32_t)cur * STA + aLane;
        uint32_t wB = wsA + (uint32_t)cur * STW + bLane;

        uint32_t af[2][4][4], bf[2][4][2];
        #pragma unroll
        for (int mi = 0; mi < 4; mi++)
            LDM_X4(af[0][mi][0], af[0][mi][1], af[0][mi][2], af[0][mi][3],
                   aB + (uint32_t)(mi * 16 * LDH) * 2);
        LDM_X4(bf[0][0][0], bf[0][0][1], bf[0][1][0], bf[0][1][1], wB);
        LDM_X4(bf[0][2][0], bf[0][2][1], bf[0][3][0], bf[0][3][1],
               wB + (uint32_t)(16 * LDH) * 2);

        #pragma unroll
        for (int ks = 0; ks < 4; ks++) {
            int cb = ks & 1, nb = cb ^ 1;
            if (ks < 3) {
                int kk = (ks + 1) * 16;
                #pragma unroll
                for (int mi = 0; mi < 4; mi++)
                    LDM_X4(af[nb][mi][0], af[nb][mi][1], af[nb][mi][2], af[nb][mi][3],
                           aB + (uint32_t)(mi * 16 * LDH + kk) * 2);
                LDM_X4(bf[nb][0][0], bf[nb][0][1], bf[nb][1][0], bf[nb][1][1],
                       wB + (uint32_t)kk * 2);
                LDM_X4(bf[nb][2][0], bf[nb][2][1], bf[nb][3][0], bf[nb][3][1],
                       wB + (uint32_t)(16 * LDH + kk) * 2);
            }
            #pragma unroll
            for (int mi = 0; mi < 4; mi++)
                #pragma unroll
                for (int nj = 0; nj < 4; nj++)
                    hmma16(acc[mi][nj], af[cb][mi], bf[cb][nj]);
        }
        __syncthreads();
    }

    // ---- epilogue: bias + residual, row LN across CTA, write x ----
    // v overwrites acc. Partial row sums into aliased smem.
    float* psum = (float*)smh;           // [8][128]
    float* psq  = psum + 8 * 128;        // [8][128]
    float* rmu  = psq + 8 * 128;         // [128]
    float* rinv = rmu + 128;             // [128]

    #pragma unroll
    for (int mi = 0; mi < 4; mi++) {
        int r0 = bm + warpM * 64 + mi * 16 + g;
        float s0 = 0.f, q0 = 0.f, s1 = 0.f, q1 = 0.f;
        #pragma unroll
        for (int nj = 0; nj < 4; nj++) {
            int c = warpN * 32 + nj * 8 + 2 * tg;
            float b0 = bias[c], b1 = bias[c + 1];
            uint32_t ra = *(uint32_t*)&x[(size_t)r0 * 256 + c];
            uint32_t rb = *(uint32_t*)&x[(size_t)(r0 + 8) * 256 + c];
            __half2 ha = *(__half2*)&ra, hb = *(__half2*)&rb;
            float v0 = acc[mi][nj][0] + b0 + __half2float(ha.x);
            float v1 = acc[mi][nj][1] + b1 + __half2float(ha.y);
            float v2 = acc[mi][nj][2] + b0 + __half2float(hb.x);
            float v3 = acc[mi][nj][3] + b1 + __half2float(hb.y);
            acc[mi][nj][0] = v0; acc[mi][nj][1] = v1;
            acc[mi][nj][2] = v2; acc[mi][nj][3] = v3;
            s0 += v0 + v1; q0 += v0 * v0 + v1 * v1;
            s1 += v2 + v3; q1 += v2 * v2 + v3 * v3;
        }
        // quad-reduce over tg
        #pragma unroll
        for (int o2 = 1; o2 <= 2; o2 <<= 1) {
            s0 += __shfl_xor_sync(0xffffffffu, s0, o2);
            q0 += __shfl_xor_sync(0xffffffffu, q0, o2);
            s1 += __shfl_xor_sync(0xffffffffu, s1, o2);
            q1 += __shfl_xor_sync(0xffffffffu, q1, o2);
        }
        if (tg == 0) {
            int lr = warpM * 64 + mi * 16 + g;
            psum[warpN * 128 + lr] = s0;
            psq [warpN * 128 + lr] = q0;
            psum[warpN * 128 + lr + 8] = s1;
            psq [warpN * 128 + lr + 8] = q1;
        }
    }
    __syncthreads();
    if (tid < 128) {
        float s = 0.f, q = 0.f;
        #pragma unroll
        for (int wN = 0; wN < 8; wN++) { s += psum[wN * 128 + tid]; q += psq[wN * 128 + tid]; }
        float mu = s * (1.f / 256.f);
        float var = q * (1.f / 256.f) - mu * mu;
        rmu[tid] = mu;
        rinv[tid] = rsqrtf(fmaxf(var, 0.f) + 1e-5f);
    }
    __syncthreads();

    #pragma unroll
    for (int mi = 0; mi < 4; mi++) {
        int lr = warpM * 64 + mi * 16 + g;
        int r0 = bm + lr;
        float mu0 = rmu[lr],     iv0 = rinv[lr];
        float mu1 = rmu[lr + 8], iv1 = rinv[lr + 8];
        #pragma unroll
        for (int nj = 0; nj < 4; nj++) {
            int c = warpN * 32 + nj * 8 + 2 * tg;
            float w0 = lnw[c], w1 = lnw[c + 1];
            float bb0 = lnb[c], bb1 = lnb[c + 1];
            *(uint32_t*)&x[(size_t)r0 * 256 + c] =
                packh2((acc[mi][nj][0] - mu0) * iv0 * w0 + bb0,
                       (acc[mi][nj][1] - mu0) * iv0 * w1 + bb1);
            *(uint32_t*)&x[(size_t)(r0 + 8) * 256 + c] =
                packh2((acc[mi][nj][2] - mu1) * iv1 * w0 + bb0,
                       (acc[mi][nj][3] - mu1) * iv1 * w1 + bb1);
        }
    }
}

// ============================ transposed-B fp16 GEMM (W given [K,N] row-major) ============
__global__ __launch_bounds__(256, 2) void hgemm_trb(
    const __half* __restrict__ A, const __half* __restrict__ W, __half* __restrict__ Cp,
    int M, int N, int K, int lda, int ldw, int ldc,
    int nsub, long sAb, long sAs, long sWb, long sWs, long sCb, long sCs)
{
    constexpr int LDH = 72;
    __shared__ __half As[128 * LDH];
    __shared__ __half Ws[128 * LDH];

    int tid = threadIdx.x, wid = tid >> 5, lane = tid & 31;
    int warpM = wid >> 2, warpN = wid & 3;
    int g = lane >> 2, tg = lane & 3;
    int bm = blockIdx.y * 128, bn = blockIdx.x * 128;
    int z = blockIdx.z, zb = z / nsub, zs = z % nsub;
    const __half* Ab = A + (size_t)zb * sAb + (size_t)zs * sAs;
    const __half* Wb = W + (size_t)zb * sWb + (size_t)zs * sWs;
    __half* Cb = Cp + (size_t)zb * sCb + (size_t)zs * sCs;

    int arow = (lane & 7) + ((lane & 8) ? 8 : 0);
    int acol = (lane & 16) ? 8 : 0;
    int brow = (lane & 7) + ((lane & 16) ? 8 : 0);
    int bcol = (lane & 8) ? 8 : 0;
    uint32_t aLane = smem_u32(As) + (uint32_t)((warpM * 64 + arow) * LDH + acol) * 2;
    uint32_t bLane = smem_u32(Ws) + (uint32_t)((warpN * 32 + brow) * LDH + bcol) * 2;

    float acc[4][4][4];
    #pragma unroll
    for (int i = 0; i < 4; i++)
        #pragma unroll
        for (int j = 0; j < 4; j++)
            #pragma unroll
            for (int q = 0; q < 4; q++) acc[i][j][q] = 0.f;

    for (int k0 = 0; k0 < K; k0 += 64) {
        __syncthreads();
        #pragma unroll
        for (int idx = tid; idx < 128 * 8; idx += 256) {
            int row = idx >> 3, q = idx & 7;
            int gm = bm + row;
            int gmc = (gm < M) ? gm : 0;
            *(uint4*)&As[row * LDH + q * 8] =
                *(const uint4*)(Ab + (size_t)gmc * lda + k0 + q * 8);
        }
        #pragma unroll
        for (int idx = tid; idx < 64 * 16; idx += 256) {
            int kk = idx >> 4, q = idx & 15;
            union { uint4 u; __half h[8]; } vv;
            vv.u = *(const uint4*)(Wb + (size_t)(k0 + kk) * ldw + bn + q * 8);
            #pragma unroll
            for (int j = 0; j < 8; j++) Ws[(q * 8 + j) * LDH + kk] = vv.h[j];
        }
        __syncthreads();

        #pragma unroll
        for (int kk = 0; kk < 64; kk += 16) {
            uint32_t af[4][4], bf[4][2];
            #pragma unroll
            for (int mi = 0; mi < 4; mi++)
                LDM_X4(af[mi][0], af[mi][1], af[mi][2], af[mi][3],
                       aLane + (uint32_t)(mi * 16 * LDH + kk) * 2);
            LDM_X4(bf[0][0], bf[0][1], bf[1][0], bf[1][1], bLane + (uint32_t)kk * 2);
            LDM_X4(bf[2][0], bf[2][1], bf[3][0], bf[3][1],
                   bLane + (uint32_t)(16 * LDH + kk) * 2);
            #pragma unroll
            for (int mi = 0; mi < 4; mi++)
                #pragma unroll
                for (int nj = 0; nj < 4; nj++)
                    hmma16(acc[mi][nj], af[mi], bf[nj]);
        }
    }

    #pragma unroll
    for (int mi = 0; mi < 4; mi++) {
        int r0 = bm + warpM * 64 + mi * 16 + g;
        #pragma unroll
        for (int nj = 0; nj < 4; nj++) {
            int c = bn + warpN * 32 + nj * 8 + 2 * tg;
            if (r0 < M)
                *(uint32_t*)&Cb[(size_t)r0 * ldc + c] = packh2(acc[mi][nj][0], acc[mi][nj][1]);
            if (r0 + 8 < M)
                *(uint32_t*)&Cb[(size_t)(r0 + 8) * ldc + c] = packh2(acc[mi][nj][2], acc[mi][nj][3]);
        }
    }
}

// ============================ persistent fused attention (one CTA per (b,h)) ==============
__global__ __launch_bounds__(256, 2) void fused_attn_h(
    const __half* __restrict__ qkv, __half* __restrict__ o, float escale)
{
    extern __shared__ __half fa_sm[];
    __half* Qs = fa_sm;
    __half* Ks = Qs + 128 * 40;
    __half* Vs = Ks + 512 * 40;

    int tid = threadIdx.x, lane = tid & 31, w = tid >> 5;
    int g = lane >> 2, tg = lane & 3;
    int z  = blockIdx.x;
    int b  = z >> 3, h = z & 7;
    const __half* base = qkv + (size_t)b * CC * 768;

    int arow = (lane & 7) + ((lane & 8) ? 8 : 0);
    int acol = (lane & 16) ? 8 : 0;
    int brow = (lane & 7) + ((lane & 16) ? 8 : 0);
    int bcol = (lane & 8) ? 8 : 0;
    uint32_t qBase = smem_u32(Qs) + (uint32_t)((w * 16 + arow) * 40 + acol) * 2;
    uint32_t kBase = smem_u32(Ks) + (uint32_t)(brow * 40 + bcol) * 2;
    uint32_t vBase = smem_u32(Vs) + (uint32_t)(brow * 520 + bcol) * 2;
    uint32_t onesAddr = smem_u32(Vs) +
        (uint32_t)((32 + (lane & 7)) * 520 + ((lane & 8) ? 8 : 0)) * 2;

    for (int idx = tid; idx < 512 * 4; idx += 256) {
        int r = idx >> 2, q4 = idx & 3;
        const __half* kr = base + (size_t)r * 768 + 256 + h * 32 + q4 * 8;
        *(uint4*)&Ks[r * 40 + q4 * 8] = *(const uint4*)kr;
        union { uint4 u; __half hh[8]; } vv;
        vv.u = *(const uint4*)(kr + 256);
        #pragma unroll
        for (int j = 0; j < 8; j++) Vs[(q4 * 8 + j) * 520 + r] = vv.hh[j];
    }
    for (int idx = tid; idx < 8 * 520; idx += 256) {
        int r = 32 + idx / 520, c = idx % 520;
        Vs[r * 520 + c] = (r == 32) ? __float2half(1.f) : __float2half(0.f);
    }
    __syncthreads();

    uint32_t bones[2];
    LDM_X2(bones[0], bones[1], onesAddr);

    const float se = escale * 1.4426950408889634f;

    for (int qt = 0; qt < 4; qt++) {
        if (qt) __syncthreads();
        #pragma unroll
        for (int idx = tid; idx < 128 * 4; idx += 256) {
            int r = idx >> 2, q4 = idx & 3;
            *(uint4*)&Qs[r * 40 + q4 * 8] =
                *(const uint4*)(base + (size_t)(qt * 128 + r) * 768 + h * 32 + q4 * 8);
        }
        __syncthreads();

        uint32_t af0[4], af1[4];
        LDM_X4(af0[0], af0[1], af0[2], af0[3], qBase);
        LDM_X4(af1[0], af1[1], af1[2], af1[3], qBase + 32u);

        float oacc[4][4];
        #pragma unroll
        for (int i = 0; i < 4; i++)
            #pragma unroll
            for (int q = 0; q < 4; q++) oacc[i][q] = 0.f;
        float smsum[4] = {0.f, 0.f, 0.f, 0.f};

        #pragma unroll 4
        for (int p8 = 0; p8 < 32; p8++) {
            uint32_t kb0[4], kb1[4];
            LDM_X4(kb0[0], kb0[1], kb0[2], kb0[3],
                   kBase + (uint32_t)(p8 * 16 * 40) * 2);
            LDM_X4(kb1[0], kb1[1], kb1[2], kb1[3],
                   kBase + (uint32_t)(p8 * 16 * 40 + 16) * 2);
            float sl[4] = {0.f, 0.f, 0.f, 0.f};
            float sh[4] = {0.f, 0.f, 0.f, 0.f};
            hmma16(sl, af0, kb0);
            hmma16(sh, af0, kb0 + 2);
            hmma16(sl, af1, kb1);
            hmma16(sh, af1, kb1 + 2);

            uint32_t a[4];
            {
                __half2 e;
                e = h2exp2(__floats2half2_rn(sl[0] * se, sl[1] * se)); a[0] = *(uint32_t*)&e;
                e = h2exp2(__floats2half2_rn(sl[2] * se, sl[3] * se)); a[1] = *(uint32_t*)&e;
                e = h2exp2(__floats2half2_rn(sh[0] * se, sh[1] * se)); a[2] = *(uint32_t*)&e;
                e = h2exp2(__floats2half2_rn(sh[2] * se, sh[3] * se)); a[3] = *(uint32_t*)&e;
            }

            uint32_t v0[4], v1[4];
            LDM_X4(v0[0], v0[1], v0[2], v0[3],
                   vBase + (uint32_t)(p8 * 16) * 2);
            LDM_X4(v1[0], v1[1], v1[2], v1[3],
                   vBase + (uint32_t)(16 * 520 + p8 * 16) * 2);
            hmma16(oacc[0], a, v0);
            hmma16(oacc[1], a, v0 + 2);
            hmma16(oacc[2], a, v1);
            hmma16(oacc[3], a, v1 + 2);
            hmma16(smsum, a, bones);
        }

        float rs0 = __shfl_sync(0xffffffffu, smsum[0], lane & ~3);
        float rs1 = __shfl_sync(0xffffffffu, smsum[2], lane & ~3);
        float inv0 = 1.f / rs0, inv1 = 1.f / rs1;
        int row0 = b * CC + qt * 128 + w * 16 + g;
        #pragma unroll
        for (int vj = 0; vj < 4; vj++) {
            int c = h * 32 + vj * 8 + 2 * tg;
            *(uint32_t*)&o[(size_t)row0 * 256 + c] =
                packh2(oacc[vj][0] * inv0, oacc[vj][1] * inv0);
            *(uint32_t*)&o[(size_t)(row0 + 8) * 256 + c] =
                packh2(oacc[vj][2] * inv1, oacc[vj][3] * inv1);
        }
    }
}

// ---------------- mask dtype detection ----------------
__global__ void detect_mask_kernel(const int* __restrict__ m) {
    __shared__ int found;
    if (threadIdx.x == 0) found = 0;
    __syncthreads();
    int idx = blockIdx.x * blockDim.x + threadIdx.x;
    unsigned v = (unsigned)m[idx];
    if (v > 1u) found = 1;
    __syncthreads();
    if (threadIdx.x == 0 && blockIdx.x == 0) g_maskmode = 0;
    __threadfence();
    if (found) g_maskmode = 1;
}

// ---------------- pool (half output) ----------------
__global__ void pool_kernel(const int* __restrict__ vi, const int* __restrict__ si,
                            const void* __restrict__ maskraw,
                            const float* __restrict__ ve, const float* __restrict__ se,
                            const float* __restrict__ lpe, const float* __restrict__ cpe,
                            __half* __restrict__ x) {
    int bc = blockIdx.x;
    int c  = bc % CC;
    int d  = threadIdx.x;
    const int* viR = vi + bc * LL;
    const int* siR = si + bc * LL;
    __shared__ int mloc[LL];
    if (threadIdx.x < LL) {
        int mv;
        if (g_maskmode == 0) mv = ((const int*)maskraw)[bc * LL + threadIdx.x];
        else                 mv = ((const unsigned char*)maskraw)[bc * LL + threadIdx.x];
        mloc[threadIdx.x] = mv;
    }
    __syncthreads();
    float acc = 0.f; int cnt = 0;
    #pragma unroll
    for (int l = 0; l < LL; l++) {
        if (mloc[l]) {
            cnt++;
            acc += ve[viR[l]*DD + d] + se[siR[l]*DD + d] + lpe[l*DD + d];
        }
    }
    x[(size_t)bc*DD + d] = __float2half(acc / (float)cnt + cpe[c*DD + d]);
}

// ---------------- warp-per-row LN for N=256 half tensors ----------------
template<int RES>
__global__ __launch_bounds__(256) void ln256(
    const __half* __restrict__ xin, const __half* __restrict__ res,
    const float* __restrict__ w, const float* __restrict__ b,
    __half* __restrict__ out)
{
    int row  = blockIdx.x * 8 + (threadIdx.x >> 5);
    int lane = threadIdx.x & 31;
    size_t off = (size_t)row * 256 + lane * 8;

    union { uint4 u; __half h[8]; } xv, rv;
    xv.u = *(const uint4*)(xin + off);
    if (RES) rv.u = *(const uint4*)(res + off);

    float v[8];
    float s = 0.f;
    #pragma unroll
    for (int j = 0; j < 8; j++) {
        float t = __half2float(xv.h[j]);
        if (RES) t += __half2float(rv.h[j]);
        v[j] = t; s += t;
    }
    #pragma unroll
    for (int o2 = 16; o2; o2 >>= 1) s += __shfl_xor_sync(0xffffffffu, s, o2);
    float mean = s * (1.f / 256.f);
    float vs = 0.f;
    #pragma unroll
    for (int j = 0; j < 8; j++) { float d = v[j] - mean; vs += d * d; }
    #pragma unroll
    for (int o2 = 16; o2; o2 >>= 1) vs += __shfl_xor_sync(0xffffffffu, vs, o2);
    float inv = rsqrtf(vs * (1.f / 256.f) + 1e-5f);

    float4 w0 = *(const float4*)(w + lane * 8);
    float4 w1 = *(const float4*)(w + lane * 8 + 4);
    float4 b0 = *(const float4*)(b + lane * 8);
    float4 b1 = *(const float4*)(b + lane * 8 + 4);
    float ww[8] = {w0.x, w0.y, w0.z, w0.w, w1.x, w1.y, w1.z, w1.w};
    float bb[8] = {b0.x, b0.y, b0.z, b0.w, b1.x, b1.y, b1.z, b1.w};

    union { uint4 u; __half h[8]; } ov;
    #pragma unroll
    for (int j = 0; j < 8; j++)
        ov.h[j] = __float2half((v[j] - mean) * inv * ww[j] + bb[j]);
    *(uint4*)(out + off) = ov.u;
}

// ---------------- generic layernorm (final N=1024 fp32 path) ----------------
__global__ void ln_kernel(const void* __restrict__ xin, int inH,
                          const void* __restrict__ res, int resM,
                          const float* __restrict__ w, const float* __restrict__ b,
                          void* __restrict__ out, int outH, int N, int resMod) {
    int row = blockIdx.x;
    int tid = threadIdx.x;
    int rrow = resMod ? (row % resMod) : row;
    int per = N >> 8;
    float v[4];
    float s = 0.f;
    for (int i = 0; i < per; i++) {
        int cI = tid + (i << 8);
        float t = inH ? __half2float(((const __half*)xin)[(size_t)row * N + cI])
                      : ((const float*)xin)[(size_t)row * N + cI];
        if (resM == 1)      t += ((const float*)res)[(size_t)rrow * N + cI];
        else if (resM == 2) t += __half2float(((const __half*)res)[(size_t)rrow * N + cI]);
        v[i] = t; s += t;
    }
    __shared__ float red[256];
    red[tid] = s; __syncthreads();
    for (int o = 128; o; o >>= 1) { if (tid < o) red[tid] += red[tid+o]; __syncthreads(); }
    float mean = red[0] / (float)N;
    __syncthreads();
    float vs = 0.f;
    for (int i = 0; i < per; i++) { float d = v[i] - mean; vs += d*d; }
    red[tid] = vs; __syncthreads();
    for (int o = 128; o; o >>= 1) { if (tid < o) red[tid] += red[tid+o]; __syncthreads(); }
    float inv = rsqrtf(red[0] / (float)N + 1e-5f);
    for (int i = 0; i < per; i++) {
        int cI = tid + (i << 8);
        float ov = (v[i] - mean) * inv * w[cI] + b[cI];
        if (outH) ((__half*)out)[(size_t)row*N + cI] = __float2half(ov);
        else      ((float*)out)[(size_t)row*N + cI] = ov;
    }
}

// ---------------- coalesced softmax: S2 [rows][512] fp32 -> half ----------------
__global__ void softmax_rows(const float* __restrict__ S, __half* __restrict__ Sh) {
    int row  = blockIdx.x * 8 + (threadIdx.x >> 5);
    int lane = threadIdx.x & 31;
    const float* r = S + (size_t)row * CC;
    __half* rh = Sh + (size_t)row * CC;
    float vals[16];
    float mx = -1e30f;
    #pragma unroll
    for (int t = 0; t < 16; t++) { vals[t] = r[lane + (t << 5)]; mx = fmaxf(mx, vals[t]); }
    for (int o = 16; o; o >>= 1) mx = fmaxf(mx, __shfl_xor_sync(0xffffffffu, mx, o));
    float sum = 0.f;
    #pragma unroll
    for (int t = 0; t < 16; t++) { vals[t] = __expf(vals[t] - mx); sum += vals[t]; }
    for (int o = 16; o; o >>= 1) sum += __shfl_xor_sync(0xffffffffu, sum, o);
    float inv = 1.f / sum;
    #pragma unroll
    for (int t = 0; t < 16; t++) rh[lane + (t << 5)] = __float2half(vals[t] * inv);
}

// ============================ host orchestration ============================
#define HG_B   hgemm<0,1,1>
#define HG_BF  hgemm<0,1,0>
#define HG_G   hgemm<1,1,1>
#define HG_N   hgemm<0,0,0>

static const int HG_SMEM = 6 * 128 * 72 * 2;                 // 110592 B
static const int HL_SMEM = 2 * (128 + 256) * 72 * 2;         // 110592 B
static const int FA_SMEM = (128*40 + 512*40 + 40*520) * 2;   // 92800 B

extern "C" void kernel_launch(void* const* d_in, const int* in_sizes, int n_in,
                              void* d_out, int out_size) {
    const int*   var_idx   = (const int*)  d_in[0];
    const int*   sign_idx  = (const int*)  d_in[1];
    const void*  lit_mask  = (const void*) d_in[2];
    const float* var_emb   = (const float*)d_in[3];
    const float* sign_emb  = (const float*)d_in[4];
    const float* litpos    = (const float*)d_in[5];
    const float* clausepos = (const float*)d_in[6];
    const float* enc_in_w  = (const float*)d_in[7];
    const float* enc_in_b  = (const float*)d_in[8];
    const float* enc_out_w = (const float*)d_in[9];
    const float* enc_out_b = (const float*)d_in[10];
    const float* enc_ff1_w = (const float*)d_in[11];
    const float* enc_ff1_b = (const float*)d_in[12];
    const float* enc_ff2_w = (const float*)d_in[13];
    const float* enc_ff2_b = (const float*)d_in[14];
    const float* n1w = (const float*)d_in[15];
    const float* n1b = (const float*)d_in[16];
    const float* n2w = (const float*)d_in[17];
    const float* n2b = (const float*)d_in[18];
    const float* th_ln_w = (const float*)d_in[19];
    const float* th_ln_b = (const float*)d_in[20];
    const float* th_w = (const float*)d_in[21];
    const float* th_b = (const float*)d_in[22];
    const float* pq   = (const float*)d_in[23];
    const float* pa_in_w  = (const float*)d_in[24];
    const float* pa_in_b  = (const float*)d_in[25];
    const float* pa_out_w = (const float*)d_in[26];
    const float* pa_out_b = (const float*)d_in[27];
    const float* pn_w = (const float*)d_in[28];
    const float* pn_b = (const float*)d_in[29];
    float* out = (float*)d_out;

    __half *x,*t0,*t1,*t2h,*ch,*qh,*qw,*S2h,*pch,*p1;
    float *S2,*p2;
    __half *hwin,*hwout,*hwf1,*hwf2,*hwth,*hwpa,*hwpo,*hwpq;
    cudaGetSymbolAddress((void**)&x,   g_x);
    cudaGetSymbolAddress((void**)&t0,  g_t0);
    cudaGetSymbolAddress((void**)&t1,  g_t1);
    cudaGetSymbolAddress((void**)&t2h, g_t2h);
    cudaGetSymbolAddress((void**)&ch,  g_ch);
    cudaGetSymbolAddress((void**)&qh,  g_qh);
    cudaGetSymbolAddress((void**)&qw,  g_qw);
    cudaGetSymbolAddress((void**)&S2,  g_S2);
    cudaGetSymbolAddress((void**)&S2h, g_S2h);
    cudaGetSymbolAddress((void**)&pch, g_pch);
    cudaGetSymbolAddress((void**)&p1,  g_p1);
    cudaGetSymbolAddress((void**)&p2,  g_p2);
    cudaGetSymbolAddress((void**)&hwin,  g_hw_in);
    cudaGetSymbolAddress((void**)&hwout, g_hw_out);
    cudaGetSymbolAddress((void**)&hwf1,  g_hw_f1);
    cudaGetSymbolAddress((void**)&hwf2,  g_hw_f2);
    cudaGetSymbolAddress((void**)&hwth,  g_hw_th);
    cudaGetSymbolAddress((void**)&hwpa,  g_hw_pa);
    cudaGetSymbolAddress((void**)&hwpo,  g_hw_po);
    cudaGetSymbolAddress((void**)&hwpq,  g_hw_pq);

    cudaFuncSetAttribute(HG_B,  cudaFuncAttributeMaxDynamicSharedMemorySize, HG_SMEM);
    cudaFuncSetAttribute(HG_BF, cudaFuncAttributeMaxDynamicSharedMemorySize, HG_SMEM);
    cudaFuncSetAttribute(HG_G,  cudaFuncAttributeMaxDynamicSharedMemorySize, HG_SMEM);
    cudaFuncSetAttribute(HG_N,  cudaFuncAttributeMaxDynamicSharedMemorySize, HG_SMEM);
    cudaFuncSetAttribute(hgemm_ln, cudaFuncAttributeMaxDynamicSharedMemorySize, HL_SMEM);
    cudaFuncSetAttribute(fused_attn_h, cudaFuncAttributeMaxDynamicSharedMemorySize, FA_SMEM);

    const int M = BB*CC;
    const float escale = 0.17677669529663687f;   // 1/sqrt(32)
    const float pscale = 0.08838834764831845f;   // 1/sqrt(128)

    cvt_all<<<2048, 256>>>(enc_in_w, enc_out_w, enc_ff1_w, enc_ff2_w,
                           th_w, pa_in_w, pa_out_w, pq,
                           hwin, hwout, hwf1, hwf2, hwth, hwpa, hwpo, hwpq);
    detect_mask_kernel<<<16, 256>>>((const int*)lit_mask);
    pool_kernel<<<M, 256>>>(var_idx, sign_idx, lit_mask, var_emb,
                            sign_emb, litpos, clausepos, x);
    HG_B<<<dim3(8,1,1),256,HG_SMEM>>>(hwpq, hwpa, pa_in_b, qh, PP,HH,HH,
                                      HH,HH,HH, 1,0,0,0,0,0,0, 0, 1.f);
    hgemm_trb<<<dim3(8,1,NHD),256>>>(qh, hwpa + (size_t)HH*HH, qw,
                                     16, HH, 128, HH, HH, HH,
                                     NHD, 0, 128, 0, (long)128*HH, 0, (long)16*HH);

    for (int i = 0; i < NLL; i++) {
        const __half* wqkv = hwin  + (size_t)i*768*DD;
        const float*  bqkv = enc_in_b  + (size_t)i*768;
        const __half* wo   = hwout + (size_t)i*DD*DD;
        const float*  bo   = enc_out_b + (size_t)i*DD;
        const __half* w1   = hwf1  + (size_t)i*HH*DD;
        const float*  b1   = enc_ff1_b + (size_t)i*HH;
        const __half* w2   = hwf2  + (size_t)i*DD*HH;
        const float*  b2   = enc_ff2_b + (size_t)i*DD;

        HG_B<<<dim3(6,128,1),256,HG_SMEM>>>(x, wqkv, bqkv, t0, M,768,DD,
                                            DD,DD,768, 1,0,0,0,0,0,0, 0, 1.f);
        fused_attn_h<<<BB*NHD, 256, FA_SMEM>>>(t0, t1, escale);
        // out-proj + bias + residual + LN  -> x
        hgemm_ln<<<dim3(1,128),512,HL_SMEM>>>(t1, wo, bo, n1w + i*DD, n1b + i*DD, x,
                                              M, DD, DD, DD);
        HG_G<<<dim3(8,128,1),256,HG_SMEM>>>(x, w1, b1, t0, M,HH,DD,
                                            DD,DD,HH, 1,0,0,0,0,0,0, 0, 1.f);
        // ff2 + bias + residual + LN -> x
        hgemm_ln<<<dim3(1,128),512,HL_SMEM>>>(t0, w2, b2, n2w + i*DD, n2b + i*DD, x,
                                              M, HH, HH, HH);
    }

    // ch = LN(x) @ th_w^T + th_b  (half)
    ln256<0><<<M/8,256>>>(x, nullptr, th_ln_w, th_ln_b, t2h);
    HG_B<<<dim3(8,128,1),256,HG_SMEM>>>(t2h, hwth, th_b, ch, M,HH,DD,
                                        DD,DD,HH, 1,0,0,0,0,0,0, 0, 1.f);

    // ---- prefix cross-attention ----
    HG_N<<<dim3(4,1,BB),256,HG_SMEM>>>(qw, ch, nullptr, S2, 128,CC,HH,
                                       HH,HH,CC, 1,
                                       0, 0, (long)CC*HH, 0, (long)128*CC, 0, 0, pscale);
    softmax_rows<<<(BB*128)/8, 256>>>(S2, S2h);
    hgemm_trb<<<dim3(8,1,BB),256>>>(S2h, ch, pch,
                                    128, HH, CC, CC, HH, HH,
                                    1, (long)128*CC, 0, (long)CC*HH, 0, (long)128*HH, 0);
    HG_B<<<dim3(1,1,BB*NHD),256,HG_SMEM>>>(pch, hwpa + (size_t)2*HH*HH, pa_in_b + 2*HH, p1,
                                           16,128,HH, HH,HH,HH, NHD,
                                           (long)128*HH, (long)16*HH, 0, (long)128*HH,
                                           (long)PP*HH, 128, 128, 1.f);
    HG_BF<<<dim3(8,4,1),256,HG_SMEM>>>(p1, hwpo, pa_out_b, p2, BB*PP,HH,HH,
                                       HH,HH,HH, 1,0,0,0,0,0,0, 0, 1.f);
    ln_kernel<<<BB*PP,256>>>(p2, 0, pq, 1, pn_w, pn_b, out, 0, HH, PP);
}